// round 16
// baseline (speedup 1.0000x reference)
#include <cuda_runtime.h>
#include <cuda_fp16.h>
#include <cstdint>

#define THREADS 256
#define NTILES  4096
#define GRID    148
#define STRIDE  (2 * GRID)

// ---- smem layout (bytes) ----
#define OFF_RING 0u        // 2 groups x 4 bufs x 8192 : A chunk [128 m][32 k] fp16, 64B rows
#define OFF_H    65536u    // 2 groups x 32768 : H [128 m][128 k] fp16, 256B rows
#define OFF_W1   131072u   // 65536 : [128 d][256 k] fp16, 512B rows
#define OFF_W2   196608u   // 8192  : [32 n][128 k] fp16, 256B rows
#define OFF_B1   204800u
#define OFF_B2   205312u
#define SMEM_TOTAL 205440u

// fp16 z in [b][y][x][ch] layout (channel-contiguous)
static __device__ __align__(16) __half g_zf[8 * 256 * 256 * 32];

__device__ __forceinline__ uint32_t smem_u32(const void* p) {
    uint32_t a;
    asm("{ .reg .u64 t; cvta.to.shared.u64 t, %1; cvt.u32.u64 %0, t; }"
        : "=r"(a) : "l"(p));
    return a;
}
__device__ __forceinline__ void ldsm4(uint32_t r[4], uint32_t addr) {
    asm volatile("ldmatrix.sync.aligned.m8n8.x4.shared.b16 {%0,%1,%2,%3}, [%4];"
                 : "=r"(r[0]), "=r"(r[1]), "=r"(r[2]), "=r"(r[3]) : "r"(addr));
}
__device__ __forceinline__ void mma16816(float c[4], const uint32_t a[4],
                                         uint32_t b0, uint32_t b1) {
    asm volatile("mma.sync.aligned.m16n8k16.row.col.f32.f16.f16.f32 "
                 "{%0,%1,%2,%3}, {%4,%5,%6,%7}, {%8,%9}, {%0,%1,%2,%3};"
                 : "+f"(c[0]), "+f"(c[1]), "+f"(c[2]), "+f"(c[3])
                 : "r"(a[0]), "r"(a[1]), "r"(a[2]), "r"(a[3]), "r"(b0), "r"(b1));
}
__device__ __forceinline__ void cp16(uint32_t dst, const void* src, bool ok) {
    asm volatile("cp.async.ca.shared.global [%0], [%1], 16, %2;"
                 :: "r"(dst), "l"(src), "r"(ok ? 16 : 0));
}
#define GBAR(g) asm volatile("bar.sync %0, 128;" :: "r"((g) + 1) : "memory")

// swizzles
__device__ __forceinline__ uint32_t swzW1(int d, int k) {   // 512B rows
    return (uint32_t)(d * 512 + (((k >> 3) ^ (d & 7)) << 4) + (k & 7) * 2);
}
__device__ __forceinline__ uint32_t swzH(int r, int k) {    // 256B rows
    return (uint32_t)(r * 256 + (((k >> 3) ^ (r & 7)) << 4) + (k & 7) * 2);
}

// per-tile staging parameters (precomputed once per tile)
struct TP {
    long long idx;      // g_zf element index of (b, y-1, x0+spx-1, 0)
    bool v, oky0, oky2, okx0, okx2;
};
__device__ __forceinline__ TP make_tp(int t, int spx) {
    TP tp;
    tp.v = (t < NTILES);
    int x0 = (t & 1) * 128, y = (t >> 1) & 255, b = t >> 9;
    int xs = x0 + spx;
    tp.idx  = ((long long)b * 65536 + (long long)(y - 1) * 256 + (xs - 1)) * 32;
    tp.oky0 = (y >= 1);  tp.oky2 = (y <= 254);
    tp.okx0 = (xs >= 1); tp.okx2 = (xs <= 254);
    return tp;
}
// issue chunk cc (0..7) of tile tp; cc constant after unroll
__device__ __forceinline__ void issue_c(const TP& tp, int cc, uint32_t bufbase,
                                        const uint32_t sg[4]) {
    int p  = cc + (cc >= 4);              // skip center tap
    int di = p / 3, dj = p - di * 3;
    bool ok = tp.v;
    if (di == 0) ok = ok && tp.oky0;
    if (di == 2) ok = ok && tp.oky2;
    if (dj == 0) ok = ok && tp.okx0;
    if (dj == 2) ok = ok && tp.okx2;
    const __half* src = ok ? (g_zf + (tp.idx + (di * 256 + dj) * 32)) : g_zf;
    #pragma unroll
    for (int i = 0; i < 4; ++i) cp16(bufbase + sg[i], src + i * 8, ok);
    asm volatile("cp.async.commit_group;");
}

// ---------------- pre-pass: fp32 z -> fp16, channel-contiguous ----------------
// thread handles 4 consecutive pixels; float4 loads, 256B contiguous stores
__global__ __launch_bounds__(256)
void zconv(const float* __restrict__ z) {
    const int b  = blockIdx.y;
    const int r  = threadIdx.x >> 6;                 // block-local row 0..3
    const int xb = (threadIdx.x & 63) * 4;           // pixel base
    const int y  = blockIdx.x * 4 + r;
    const float* src = z + (((size_t)b * 32) * 256 + y) * 256 + xb;
    uint32_t h[4][16];
    #pragma unroll
    for (int i = 0; i < 16; ++i) {
        float4 a = *(const float4*)(src + (size_t)(2 * i) * 65536);
        float4 c = *(const float4*)(src + (size_t)(2 * i + 1) * 65536);
        __half2 t0 = __floats2half2_rn(a.x, c.x);
        __half2 t1 = __floats2half2_rn(a.y, c.y);
        __half2 t2 = __floats2half2_rn(a.z, c.z);
        __half2 t3 = __floats2half2_rn(a.w, c.w);
        h[0][i] = *(uint32_t*)&t0; h[1][i] = *(uint32_t*)&t1;
        h[2][i] = *(uint32_t*)&t2; h[3][i] = *(uint32_t*)&t3;
    }
    #pragma unroll
    for (int px = 0; px < 4; ++px) {
        uint4* d = (uint4*)(g_zf + (((size_t)b * 256 + y) * 256 + xb + px) * 32);
        #pragma unroll
        for (int i = 0; i < 4; ++i)
            d[i] = make_uint4(h[px][4*i], h[px][4*i+1], h[px][4*i+2], h[px][4*i+3]);
    }
}

// ---------------- main kernel: 2 independent 4-warp groups ----------------
__global__ __launch_bounds__(THREADS, 1)
void lp_mma(const float* __restrict__ W1, const float* __restrict__ b1,
            const float* __restrict__ W2, const float* __restrict__ b2,
            float* __restrict__ out)
{
    extern __shared__ __align__(16) char smem[];
    const uint32_t sb = smem_u32(smem);
    const int tid  = threadIdx.x;
    const int g    = tid >> 7;            // group 0/1
    const int gtid = tid & 127;
    const int w    = gtid >> 5;           // warp within group 0..3
    const int lane = tid & 31;

    // ---------- one-time weight staging ----------
    for (int idx = tid; idx < 128 * 256; idx += THREADS) {
        int d = idx >> 8, k = idx & 255;
        int q = k >> 5, ch = k & 31;
        int p = q + (q >= 4);                 // skip center tap
        *(__half*)(smem + OFF_W1 + swzW1(d, k)) = __float2half(W1[d * 288 + ch * 9 + p]);
    }
    for (int idx = tid; idx < 32 * 128; idx += THREADS) {
        int n = idx >> 7, k = idx & 127;
        *(__half*)(smem + OFF_W2 + swzH(n, k)) = __float2half(W2[n * 128 + k]);
    }
    if (tid < 128) ((float*)(smem + OFF_B1))[tid] = b1[tid];
    if (tid < 32)  ((float*)(smem + OFF_B2))[tid] = b2[tid];
    __syncthreads();

    // ---------- per-group bases ----------
    const uint32_t ringb = sb + OFF_RING + (uint32_t)g * 32768u;
    const uint32_t Hb    = sb + OFF_H    + (uint32_t)g * 32768u;

    // ---------- warp tiling / lane addressing ----------
    const int mw = w & 1;                 // layer-1 M slice (64 rows)
    const int nw = w >> 1;                // layer-1 N slice (64 cols)
    const int arow  = lane & 15;
    const int kselA = lane >> 4;
    const int brow  = ((lane >> 4) << 3) + (lane & 7);
    const int kselB = (lane >> 3) & 1;
    const int xorA2 = (arow >> 1) & 3;    // 64B-row A buffer granule XOR
    const int xorAH = arow & 7;           // 256B-row H granule XOR
    const int xorB  = brow & 7;

    uint32_t rowA1[4];
    #pragma unroll
    for (int mi = 0; mi < 4; ++mi)
        rowA1[mi] = (uint32_t)((mw * 64 + mi * 16 + arow) * 64);
    uint32_t rowB1[4];
    #pragma unroll
    for (int jq = 0; jq < 4; ++jq)
        rowB1[jq] = sb + OFF_W1 + (uint32_t)((nw * 64 + jq * 16 + brow) * 512);
    uint32_t rowA2[2];
    #pragma unroll
    for (int mi = 0; mi < 2; ++mi)
        rowA2[mi] = (uint32_t)((w * 32 + mi * 16 + arow) * 256);
    uint32_t rowB2[2] = { sb + OFF_W2 + (uint32_t)(brow * 256),
                          sb + OFF_W2 + (uint32_t)((16 + brow) * 256) };

    // staging: group thread -> pixel; chunk = 1 tap x 32 ch (8KB), 64B/thread
    const int spx = gtid;
    uint32_t sg[4];
    #pragma unroll
    for (int i = 0; i < 4; ++i)
        sg[i] = (uint32_t)(spx * 64 + ((i ^ ((spx >> 1) & 3)) << 4));

    const float* b1s = (const float*)(smem + OFF_B1);
    const float* b2s = (const float*)(smem + OFF_B2);

    const int t0 = 2 * blockIdx.x + g;
    TP cur = make_tp(t0, spx);
    TP nxt = make_tp(t0 + STRIDE, spx);

    // prologue: chunks 0,1 of first tile -> bufs 0,1
    issue_c(cur, 0, ringb, sg);
    issue_c(cur, 1, ringb + 8192u, sg);

    for (int t = t0; t < NTILES; t += STRIDE) {
        const int x0 = (t & 1) * 128;
        const int y  = (t >> 1) & 255;
        const int b  = t >> 9;

        float C[4][8][4];
        #pragma unroll
        for (int mi = 0; mi < 4; ++mi)
            #pragma unroll
            for (int jo = 0; jo < 8; ++jo)
                #pragma unroll
                for (int r = 0; r < 4; ++r) C[mi][jo][r] = 0.0f;

        // ==== layer 1: 8 chunks of K=32, 4-deep ring, lookahead-2 ====
        #pragma unroll
        for (int c = 0; c < 8; ++c) {
            const uint32_t ibase = ringb + (uint32_t)(((c + 2) & 3) * 8192);
            if (c < 6) issue_c(cur, c + 2, ibase, sg);
            else       issue_c(nxt, c - 6, ibase, sg);
            asm volatile("cp.async.wait_group 2;");
            GBAR(g);

            const uint32_t Ab = ringb + (uint32_t)((c & 3) * 8192);
            #pragma unroll
            for (int s = 0; s < 2; ++s) {
                const uint32_t koA = (uint32_t)((((2 * s + kselA) ^ xorA2) & 3) << 4);
                const uint32_t koB = (uint32_t)(((c * 4 + 2 * s + kselB) ^ xorB) << 4);
                uint32_t ah[4][4], bfr[4][4];
                #pragma unroll
                for (int mi = 0; mi < 4; ++mi) ldsm4(ah[mi], Ab + rowA1[mi] + koA);
                #pragma unroll
                for (int jq = 0; jq < 4; ++jq) ldsm4(bfr[jq], rowB1[jq] + koB);
                #pragma unroll
                for (int mi = 0; mi < 4; ++mi)
                    #pragma unroll
                    for (int jo = 0; jo < 8; ++jo)
                        mma16816(C[mi][jo], ah[mi],
                                 bfr[jo >> 1][(jo & 1) * 2], bfr[jo >> 1][(jo & 1) * 2 + 1]);
            }
        }

        // ---- epilogue 1: bias + ReLU -> fp16 H (group-private) ----
        {
            const int c2l = (lane & 3) * 2;
            #pragma unroll
            for (int mi = 0; mi < 4; ++mi) {
                int row0 = mw * 64 + mi * 16 + (lane >> 2);
                #pragma unroll
                for (int jo = 0; jo < 8; ++jo) {
                    int n = nw * 64 + jo * 8 + c2l;
                    float bA = b1s[n], bB = b1s[n + 1];
                    __half2 u = __floats2half2_rn(fmaxf(C[mi][jo][0] + bA, 0.0f),
                                                  fmaxf(C[mi][jo][1] + bB, 0.0f));
                    __half2 v = __floats2half2_rn(fmaxf(C[mi][jo][2] + bA, 0.0f),
                                                  fmaxf(C[mi][jo][3] + bB, 0.0f));
                    *(uint32_t*)(smem + (Hb - sb) + swzH(row0, n))     = *(uint32_t*)&u;
                    *(uint32_t*)(smem + (Hb - sb) + swzH(row0 + 8, n)) = *(uint32_t*)&v;
                }
            }
        }
        GBAR(g);

        // ============ layer 2: m32 per warp, N=32, K=128 ============
        float C2[2][4][4];
        #pragma unroll
        for (int mi = 0; mi < 2; ++mi)
            #pragma unroll
            for (int jo = 0; jo < 4; ++jo)
                #pragma unroll
                for (int r = 0; r < 4; ++r) C2[mi][jo][r] = 0.0f;

        #pragma unroll
        for (int s = 0; s < 8; ++s) {
            const uint32_t koA = (uint32_t)(((2 * s + kselA) ^ xorAH) << 4);
            const uint32_t koB = (uint32_t)(((2 * s + kselB) ^ xorB) << 4);
            uint32_t a2[2][4], bfr[2][4];
            #pragma unroll
            for (int mi = 0; mi < 2; ++mi) ldsm4(a2[mi], Hb + rowA2[mi] + koA);
            #pragma unroll
            for (int jq = 0; jq < 2; ++jq) ldsm4(bfr[jq], rowB2[jq] + koB);
            #pragma unroll
            for (int mi = 0; mi < 2; ++mi)
                #pragma unroll
                for (int jo = 0; jo < 4; ++jo)
                    mma16816(C2[mi][jo], a2[mi],
                             bfr[jo >> 1][(jo & 1) * 2], bfr[jo >> 1][(jo & 1) * 2 + 1]);
        }

        // ---- epilogue 2: bias + store (warp stores its m32) ----
        {
            #pragma unroll
            for (int mi = 0; mi < 2; ++mi) {
                const int m = w * 32 + mi * 16 + (lane >> 2);
                #pragma unroll
                for (int jo = 0; jo < 4; ++jo) {
                    int n = jo * 8 + (lane & 3) * 2;
                    float* po = out + ((size_t)(b * 32 + n)) * 65536 + y * 256 + x0 + m;
                    po[0]         = C2[mi][jo][0] + b2s[n];
                    po[65536]     = C2[mi][jo][1] + b2s[n + 1];
                    po[8]         = C2[mi][jo][2] + b2s[n];
                    po[8 + 65536] = C2[mi][jo][3] + b2s[n + 1];
                }
            }
        }

        // advance tile-parameter pipeline
        cur = nxt;
        nxt = make_tp(t + 2 * STRIDE, spx);
    }
}

extern "C" void kernel_launch(void* const* d_in, const int* in_sizes, int n_in,
                              void* d_out, int out_size) {
    const float* z  = (const float*)d_in[0];
    const float* W1 = (const float*)d_in[1];
    const float* b1 = (const float*)d_in[2];
    const float* W2 = (const float*)d_in[3];
    const float* b2 = (const float*)d_in[4];
    float* out = (float*)d_out;

    zconv<<<dim3(64, 8), 256>>>(z);
    cudaFuncSetAttribute(lp_mma, cudaFuncAttributeMaxDynamicSharedMemorySize,
                         SMEM_TOTAL);
    lp_mma<<<GRID, THREADS, SMEM_TOTAL>>>(W1, b1, W2, b2, out);
}

// round 17
// speedup vs baseline: 1.1372x; 1.1372x over previous
#include <cuda_runtime.h>
#include <cuda_fp16.h>
#include <cstdint>

#define THREADS 512
#define NTILES  4096
#define GRID    148
#define STRIDE  (2 * GRID)

// ---- smem layout (bytes) ----
#define OFF_RING 0u        // 2 groups x 3 pair-slots x 16384 (pair = 2 chunks of 8KB)
#define OFF_PS   98304u    // 2 groups x 16896 : fp32 [32 n][132 m-padded]
#define OFF_W1   132096u   // 65536 : [128 d][256 k] fp16, 512B rows
#define OFF_W2   197632u   // 8192  : [32 n][128 k] fp16, 256B rows
#define OFF_B1   205824u
#define OFF_B2   206336u
#define SMEM_TOTAL 206464u

// fp16 z in [b][y][x][ch] layout (channel-contiguous)
static __device__ __align__(16) __half g_zf[8 * 256 * 256 * 32];

__device__ __forceinline__ uint32_t smem_u32(const void* p) {
    uint32_t a;
    asm("{ .reg .u64 t; cvta.to.shared.u64 t, %1; cvt.u32.u64 %0, t; }"
        : "=r"(a) : "l"(p));
    return a;
}
__device__ __forceinline__ void ldsm4(uint32_t r[4], uint32_t addr) {
    asm volatile("ldmatrix.sync.aligned.m8n8.x4.shared.b16 {%0,%1,%2,%3}, [%4];"
                 : "=r"(r[0]), "=r"(r[1]), "=r"(r[2]), "=r"(r[3]) : "r"(addr));
}
__device__ __forceinline__ void mma16816(float c[4], const uint32_t a[4],
                                         uint32_t b0, uint32_t b1) {
    asm volatile("mma.sync.aligned.m16n8k16.row.col.f32.f16.f16.f32 "
                 "{%0,%1,%2,%3}, {%4,%5,%6,%7}, {%8,%9}, {%0,%1,%2,%3};"
                 : "+f"(c[0]), "+f"(c[1]), "+f"(c[2]), "+f"(c[3])
                 : "r"(a[0]), "r"(a[1]), "r"(a[2]), "r"(a[3]), "r"(b0), "r"(b1));
}
__device__ __forceinline__ void cp16(uint32_t dst, const void* src, bool ok) {
    asm volatile("cp.async.ca.shared.global [%0], [%1], 16, %2;"
                 :: "r"(dst), "l"(src), "r"(ok ? 16 : 0));
}
__device__ __forceinline__ uint32_t pack_h2(float a, float b) {
    __half2 t = __floats2half2_rn(a, b);
    return *(uint32_t*)&t;
}
#define GBAR(g) asm volatile("bar.sync %0, 256;" :: "r"((g) + 1) : "memory")

// swizzles
__device__ __forceinline__ uint32_t swzW1(int d, int k) {   // 512B rows
    return (uint32_t)(d * 512 + (((k >> 3) ^ (d & 7)) << 4) + (k & 7) * 2);
}
__device__ __forceinline__ uint32_t swzH(int r, int k) {    // 256B rows
    return (uint32_t)(r * 256 + (((k >> 3) ^ (r & 7)) << 4) + (k & 7) * 2);
}

// per-tile staging parameters
struct TP {
    long long idx;      // g_zf element index of (b, y-1, x0+spx-1, sq*16)
    bool v, oky0, oky2, okx0, okx2;
};
__device__ __forceinline__ TP make_tp(int t, int spx, int sq) {
    TP tp;
    tp.v = (t < NTILES);
    int x0 = (t & 1) * 128, y = (t >> 1) & 255, b = t >> 9;
    int xs = x0 + spx;
    tp.idx  = ((long long)b * 65536 + (long long)(y - 1) * 256 + (xs - 1)) * 32 + sq * 16;
    tp.oky0 = (y >= 1);  tp.oky2 = (y <= 254);
    tp.okx0 = (xs >= 1); tp.okx2 = (xs <= 254);
    return tp;
}
// issue ONE chunk cc (0..7); constant cc folds predicates/offsets
__device__ __forceinline__ void chunk_cp(const TP& tp, int cc, uint32_t bufbase,
                                         uint32_t sg0, uint32_t sg1) {
    int p  = cc + (cc >= 4);              // skip center tap
    int di = p / 3, dj = p - di * 3;
    bool ok = tp.v;
    if (di == 0) ok = ok && tp.oky0;
    if (di == 2) ok = ok && tp.oky2;
    if (dj == 0) ok = ok && tp.okx0;
    if (dj == 2) ok = ok && tp.okx2;
    const __half* src = ok ? (g_zf + (tp.idx + (di * 256 + dj) * 32)) : g_zf;
    cp16(bufbase + sg0, src, ok);
    cp16(bufbase + sg1, src + 8, ok);
}
// issue a PAIR (chunks 2j, 2j+1) as ONE commit group
__device__ __forceinline__ void issue_pair(const TP& tp, int j, uint32_t slotbase,
                                           uint32_t sg0, uint32_t sg1) {
    chunk_cp(tp, 2 * j,     slotbase,         sg0, sg1);
    chunk_cp(tp, 2 * j + 1, slotbase + 8192u, sg0, sg1);
    asm volatile("cp.async.commit_group;");
}

// ---------------- pre-pass: fp32 z -> fp16, channel-contiguous ----------------
__global__ __launch_bounds__(256)
void zconv(const float* __restrict__ z) {
    const int y = blockIdx.x, b = blockIdx.y, x = threadIdx.x;
    const float* src = z + (((size_t)b * 32) * 256 + y) * 256 + x;
    float v[32];
    #pragma unroll
    for (int ch = 0; ch < 32; ++ch) v[ch] = src[(size_t)ch * 65536];
    uint32_t h[16];
    #pragma unroll
    for (int i = 0; i < 16; ++i) h[i] = pack_h2(v[2 * i], v[2 * i + 1]);
    uint4* d = (uint4*)(g_zf + (((size_t)b * 256 + y) * 256 + x) * 32);
    #pragma unroll
    for (int i = 0; i < 4; ++i)
        d[i] = make_uint4(h[4*i], h[4*i+1], h[4*i+2], h[4*i+3]);
}

// ---------------- main kernel: 2 independent 8-warp groups ----------------
__global__ __launch_bounds__(THREADS, 1)
void lp_mma(const float* __restrict__ W1, const float* __restrict__ b1,
            const float* __restrict__ W2, const float* __restrict__ b2,
            float* __restrict__ out)
{
    extern __shared__ __align__(16) char smem[];
    const uint32_t sb = smem_u32(smem);
    const int tid  = threadIdx.x;
    const int g    = tid >> 8;            // group 0/1
    const int gtid = tid & 255;
    const int w    = gtid >> 5;           // warp within group 0..7
    const int lane = tid & 31;

    // ---------- one-time weight staging ----------
    for (int idx = tid; idx < 128 * 256; idx += THREADS) {
        int d = idx >> 8, k = idx & 255;
        int q = k >> 5, ch = k & 31;
        int p = q + (q >= 4);                 // skip center tap
        *(__half*)(smem + OFF_W1 + swzW1(d, k)) = __float2half(W1[d * 288 + ch * 9 + p]);
    }
    for (int idx = tid; idx < 32 * 128; idx += THREADS) {
        int n = idx >> 7, k = idx & 127;
        *(__half*)(smem + OFF_W2 + swzH(n, k)) = __float2half(W2[n * 128 + k]);
    }
    if (tid < 128) ((float*)(smem + OFF_B1))[tid] = b1[tid];
    if (tid < 32)  ((float*)(smem + OFF_B2))[tid] = b2[tid];
    __syncthreads();

    // ---------- per-group bases ----------
    const uint32_t ringb = sb + OFF_RING + (uint32_t)g * 49152u;
    float* psg = (float*)(smem + OFF_PS + (uint32_t)g * 16896u);

    // ---------- warp tiling / lane addressing ----------
    const int mw = w & 3;                 // layer-1 M slice (32 rows)
    const int nw = w >> 2;                // layer-1 N slice (64 cols)
    const int arow  = lane & 15;
    const int kselA = lane >> 4;
    const int brow  = ((lane >> 4) << 3) + (lane & 7);
    const int kselB = (lane >> 3) & 1;
    const int xorA2 = (arow >> 1) & 3;    // 64B-row A buffer granule XOR
    const int xorB  = brow & 7;

    uint32_t rowA1[2];
    #pragma unroll
    for (int mi = 0; mi < 2; ++mi)
        rowA1[mi] = (uint32_t)((mw * 32 + mi * 16 + arow) * 64);
    uint32_t rowB1[4];
    #pragma unroll
    for (int jq = 0; jq < 4; ++jq)
        rowB1[jq] = sb + OFF_W1 + (uint32_t)((nw * 64 + jq * 16 + brow) * 512);
    uint32_t rowB2[2] = { sb + OFF_W2 + (uint32_t)(brow * 256),
                          sb + OFF_W2 + (uint32_t)((16 + brow) * 256) };

    // staging: group thread -> (pixel, ch-half); chunk = 1 tap x 32 ch (8KB)
    const int spx = gtid >> 1;
    const int sq  = gtid & 1;
    const uint32_t sg0 = (uint32_t)(spx * 64 + (((2 * sq)     ^ ((spx >> 1) & 3)) << 4));
    const uint32_t sg1 = (uint32_t)(spx * 64 + (((2 * sq + 1) ^ ((spx >> 1) & 3)) << 4));

    const float* b1s = (const float*)(smem + OFF_B1);
    const float* b2s = (const float*)(smem + OFF_B2);

    const int t0 = 2 * blockIdx.x + g;
    TP cur = make_tp(t0, spx, sq);
    TP nxt = make_tp(t0 + STRIDE, spx, sq);

    // prologue: pairs 0,1 of first tile -> slots 0,1
    issue_pair(cur, 0, ringb, sg0, sg1);
    issue_pair(cur, 1, ringb + 16384u, sg0, sg1);
    int ib = 2, cb = 0;                   // pair-slot counters (mod 3)

    for (int t = t0; t < NTILES; t += STRIDE) {
        const int x0 = (t & 1) * 128;
        const int y  = (t >> 1) & 255;
        const int b  = t >> 9;

        float C[2][8][4];
        #pragma unroll
        for (int mi = 0; mi < 2; ++mi)
            #pragma unroll
            for (int jo = 0; jo < 8; ++jo)
                #pragma unroll
                for (int r = 0; r < 4; ++r) C[mi][jo][r] = 0.0f;

        // ==== layer 1: 4 pairs (2 chunks each), 3-slot ring, lookahead-2 pairs ====
        #pragma unroll
        for (int j = 0; j < 4; ++j) {
            asm volatile("cp.async.wait_group 1;");
            GBAR(g);
            {   // issue pair j+2 (occupant pair j-1 consumed before GBAR_j -> safe)
                const uint32_t slot = ringb + (uint32_t)(ib * 16384);
                ib = (ib == 2) ? 0 : ib + 1;
                if (j < 2) issue_pair(cur, j + 2, slot, sg0, sg1);
                else       issue_pair(nxt, j - 2, slot, sg0, sg1);
            }
            const uint32_t Ab = ringb + (uint32_t)(cb * 16384);
            cb = (cb == 2) ? 0 : cb + 1;
            #pragma unroll
            for (int h = 0; h < 2; ++h) {           // chunk within pair
                const int c = 2 * j + h;
                const uint32_t Ac = Ab + (uint32_t)(h * 8192);
                #pragma unroll
                for (int s = 0; s < 2; ++s) {
                    const uint32_t koA = (uint32_t)((((2 * s + kselA) ^ xorA2) & 3) << 4);
                    const uint32_t koB = (uint32_t)(((c * 4 + 2 * s + kselB) ^ xorB) << 4);
                    uint32_t ah[2][4], bfr[4][4];
                    #pragma unroll
                    for (int mi = 0; mi < 2; ++mi) ldsm4(ah[mi], Ac + rowA1[mi] + koA);
                    #pragma unroll
                    for (int jq = 0; jq < 4; ++jq) ldsm4(bfr[jq], rowB1[jq] + koB);
                    #pragma unroll
                    for (int mi = 0; mi < 2; ++mi)
                        #pragma unroll
                        for (int jo = 0; jo < 8; ++jo)
                            mma16816(C[mi][jo], ah[mi],
                                     bfr[jo >> 1][(jo & 1) * 2], bfr[jo >> 1][(jo & 1) * 2 + 1]);
                }
            }
        }

        // ==== epilogue 1 in registers: C -> layer-2 A fragments (no smem) ====
        uint32_t a2[2][4][4];
        {
            const int c2l = (lane & 3) * 2;
            #pragma unroll
            for (int mi = 0; mi < 2; ++mi) {
                #pragma unroll
                for (int kc = 0; kc < 4; ++kc) {
                    int n0 = nw * 64 + kc * 16 + c2l;
                    float bA = b1s[n0], bB = b1s[n0 + 1];
                    a2[mi][kc][0] = pack_h2(fmaxf(C[mi][2*kc][0] + bA, 0.0f),
                                            fmaxf(C[mi][2*kc][1] + bB, 0.0f));
                    a2[mi][kc][1] = pack_h2(fmaxf(C[mi][2*kc][2] + bA, 0.0f),
                                            fmaxf(C[mi][2*kc][3] + bB, 0.0f));
                    float bC = b1s[n0 + 8], bD = b1s[n0 + 9];
                    a2[mi][kc][2] = pack_h2(fmaxf(C[mi][2*kc+1][0] + bC, 0.0f),
                                            fmaxf(C[mi][2*kc+1][1] + bD, 0.0f));
                    a2[mi][kc][3] = pack_h2(fmaxf(C[mi][2*kc+1][2] + bC, 0.0f),
                                            fmaxf(C[mi][2*kc+1][3] + bD, 0.0f));
                }
            }
        }

        // ==== layer 2: split-K over nw (K=64 per warp), M32, N=32 ====
        float C2[2][4][4];
        #pragma unroll
        for (int mi = 0; mi < 2; ++mi)
            #pragma unroll
            for (int jo = 0; jo < 4; ++jo)
                #pragma unroll
                for (int r = 0; r < 4; ++r) C2[mi][jo][r] = 0.0f;

        #pragma unroll
        for (int kc = 0; kc < 4; ++kc) {
            // B k-granule matches this warp's hidden slice (k = nw*64 + kc*16)
            const uint32_t koB = (uint32_t)(((nw * 8 + 2 * kc + kselB) ^ xorB) << 4);
            uint32_t bfr[2][4];
            #pragma unroll
            for (int jq = 0; jq < 2; ++jq) ldsm4(bfr[jq], rowB2[jq] + koB);
            #pragma unroll
            for (int mi = 0; mi < 2; ++mi)
                #pragma unroll
                for (int jo = 0; jo < 4; ++jo)
                    mma16816(C2[mi][jo], a2[mi][kc],
                             bfr[jo >> 1][(jo & 1) * 2], bfr[jo >> 1][(jo & 1) * 2 + 1]);
        }

        // ---- split-K reduce: nw=1 warps store partials, nw=0 reduce+store ----
        {
            const int r0 = lane >> 2, c2l = (lane & 3) * 2;
            if (nw == 1) {
                #pragma unroll
                for (int mi = 0; mi < 2; ++mi) {
                    int m = mw * 32 + mi * 16 + r0;
                    #pragma unroll
                    for (int jo = 0; jo < 4; ++jo) {
                        int n = jo * 8 + c2l;
                        psg[n * 132 + m]           = C2[mi][jo][0];
                        psg[(n + 1) * 132 + m]     = C2[mi][jo][1];
                        psg[n * 132 + m + 8]       = C2[mi][jo][2];
                        psg[(n + 1) * 132 + m + 8] = C2[mi][jo][3];
                    }
                }
            }
            GBAR(g);
            if (nw == 0) {
                #pragma unroll
                for (int mi = 0; mi < 2; ++mi) {
                    int m = mw * 32 + mi * 16 + r0;
                    #pragma unroll
                    for (int jo = 0; jo < 4; ++jo) {
                        int n = jo * 8 + c2l;
                        float* po = out + ((size_t)(b * 32 + n)) * 65536 + y * 256 + x0 + m;
                        po[0]         = C2[mi][jo][0] + psg[n * 132 + m]           + b2s[n];
                        po[65536]     = C2[mi][jo][1] + psg[(n + 1) * 132 + m]     + b2s[n + 1];
                        po[8]         = C2[mi][jo][2] + psg[n * 132 + m + 8]       + b2s[n];
                        po[8 + 65536] = C2[mi][jo][3] + psg[(n + 1) * 132 + m + 8] + b2s[n + 1];
                    }
                }
            }
        }

        // advance tile-parameter pipeline
        cur = nxt;
        nxt = make_tp(t + 2 * STRIDE, spx, sq);
    }
}

extern "C" void kernel_launch(void* const* d_in, const int* in_sizes, int n_in,
                              void* d_out, int out_size) {
    const float* z  = (const float*)d_in[0];
    const float* W1 = (const float*)d_in[1];
    const float* b1 = (const float*)d_in[2];
    const float* W2 = (const float*)d_in[3];
    const float* b2 = (const float*)d_in[4];
    float* out = (float*)d_out;

    zconv<<<dim3(256, 8), 256>>>(z);
    cudaFuncSetAttribute(lp_mma, cudaFuncAttributeMaxDynamicSharedMemorySize,
                         SMEM_TOTAL);
    lp_mma<<<GRID, THREADS, SMEM_TOTAL>>>(W1, b1, W2, b2, out);
}